// round 15
// baseline (speedup 1.0000x reference)
#include <cuda_runtime.h>
#include <cuda_fp16.h>
#include <cstdint>
#include <math.h>

#define T_STEPS 64
#define B_DIM 2048
#define U_DIM 1024
#define NTILE_U 8             // 1024/128 u-tiles
#define NTILE_B 16            // 2048/128 b-tiles
#define KB 64                 // k elements per chunk
#define NCHUNK (U_DIM / KB)   // 16

// ---------------- persistent state (no allocs allowed) ----------------
__device__ __align__(128) __half g_h_hi[2][B_DIM * U_DIM];
__device__ __align__(128) __half g_h_lo[2][B_DIM * U_DIM];
__device__ __align__(128) __half g_Rt[2 * U_DIM * U_DIM];   // Rt[n][k] = R[k][n], rounded fp16
__device__ float g_x1[2][B_DIM];
__device__ float g_x2[2][B_DIM];
__device__ float g_part[B_DIM][NTILE_U];
__device__ int   g_tick[T_STEPS][NTILE_B];

// ---------------- PTX helpers (base-sm_103-safe) ----------------
__device__ __forceinline__ uint32_t smem_u32(const void* p) {
    uint32_t a;
    asm("{ .reg .u64 t; cvta.to.shared.u64 t, %1; cvt.u32.u64 %0, t; }" : "=r"(a) : "l"(p));
    return a;
}
#define CP16(s, g) \
    asm volatile("cp.async.cg.shared.global [%0], [%1], 16;" :: "r"(s), "l"(g) : "memory")
#define CP_COMMIT() asm volatile("cp.async.commit_group;" ::: "memory")
#define CP_WAIT1()  asm volatile("cp.async.wait_group 1;" ::: "memory")
#define CP_WAIT0()  asm volatile("cp.async.wait_group 0;" ::: "memory")

#define LDSM_X4(r, addr) \
    asm volatile("ldmatrix.sync.aligned.m8n8.x4.shared.b16 {%0,%1,%2,%3}, [%4];" \
        : "=r"((r)[0]), "=r"((r)[1]), "=r"((r)[2]), "=r"((r)[3]) : "r"(addr))

__device__ __forceinline__ void mma_f16(float* d, const uint32_t* a, const uint32_t* b) {
    asm volatile("mma.sync.aligned.m16n8k16.row.col.f32.f16.f16.f32 "
        "{%0,%1,%2,%3}, {%4,%5,%6,%7}, {%8,%9}, {%0,%1,%2,%3};"
        : "+f"(d[0]), "+f"(d[1]), "+f"(d[2]), "+f"(d[3])
        : "r"(a[0]), "r"(a[1]), "r"(a[2]), "r"(a[3]), "r"(b[0]), "r"(b[1]));
}

// SMEM stage layout: 4 tiles of 128 rows x 64 k fp16, padded row stride 144 B
// (144 = 16*9; 9r mod 8 bijective over 8 rows => conflict-free ldmatrix phases)
#define RS 144
#define TILE_B (128 * RS)       // 18432
#define ST_A_HI 0
#define ST_A_LO (1 * TILE_B)
#define ST_BF   (2 * TILE_B)
#define ST_BC   (3 * TILE_B)
#define STAGE (4 * TILE_B)      // 73728
#define NSTAGE 3
#define SMEM_HDR 3072           // red[128][4] floats (2048) + sflag + pad
#define SMEM_REQ (SMEM_HDR + NSTAGE * STAGE)   // 224256 B < 227 KB cap

// ---------------- init kernels ----------------
__global__ void init_state(const float* __restrict__ x1_0,
                           const float* __restrict__ x2_0,
                           const float* __restrict__ c0) {
    int i = blockIdx.x * blockDim.x + threadIdx.x;
    int stride = gridDim.x * blockDim.x;
    if (i < B_DIM) { g_x1[0][i] = x1_0[i]; g_x2[0][i] = x2_0[i]; }
    if (i < T_STEPS * NTILE_B) ((int*)g_tick)[i] = 0;
    for (int j = i; j < B_DIM * U_DIM; j += stride) {
        float v = c0[j];
        __half hi = __float2half_rn(v);
        g_h_hi[0][j] = hi;
        g_h_lo[0][j] = __float2half_rn(v - __half2float(hi));
    }
}

// Transpose R (U x 2U, row-major) -> Rt (2U x U), rounded to fp16.
__global__ void transpose_R(const float* __restrict__ R) {
    __shared__ float tile[32][33];
    const int nb = blockIdx.x * 32;   // n tile (0..2047)
    const int kb = blockIdx.y * 32;   // k tile (0..1023)
    const int tx = threadIdx.x, ty = threadIdx.y;
    for (int kk = ty; kk < 32; kk += 8)
        tile[kk][tx] = R[(kb + kk) * (2 * U_DIM) + nb + tx];
    __syncthreads();
    for (int nn = ty; nn < 32; nn += 8)
        g_Rt[(size_t)(nb + nn) * U_DIM + kb + tx] = __float2half_rn(tile[tx][nn]);
}

// ---------------- main step kernel ----------------
// grid (8 u-tiles, 16 b-tiles) = 128 CTAs, 512 threads, occ 1 => one CTA per SM.
__global__ __launch_bounds__(512, 1)
void step_gemm(const float* __restrict__ Kmat,   // (2U)
               const float* __restrict__ bias,   // (2U)
               const float* __restrict__ wout,   // (U)
               const float* __restrict__ inp,    // (T, B)
               float* __restrict__ out,          // (T, B)
               int t)
{
    extern __shared__ char smem[];
    float* red = (float*)smem;                 // [128][4]
    int* sflag = (int*)(smem + 2048);
    const uint32_t sb = smem_u32(smem);
    const uint32_t tiles = sb + SMEM_HDR;
    const int par = t & 1;

    const int tid  = threadIdx.x;
    const int lane = tid & 31;
    const int wid  = tid >> 5;                 // 0..15
    const int mwarp = wid & 3;                 // 4 x 32 rows
    const int nwarp = wid >> 2;                // 4 x 32 cols
    const int b0 = blockIdx.y * 128;
    const int u0 = blockIdx.x * 128;

    const __half* __restrict__ pAh = g_h_hi[par] + (size_t)b0 * U_DIM;
    const __half* __restrict__ pAl = g_h_lo[par] + (size_t)b0 * U_DIM;
    const __half* __restrict__ pBf = g_Rt + (size_t)u0 * U_DIM;
    const __half* __restrict__ pBc = g_Rt + (size_t)(U_DIM + u0) * U_DIM;

    // cp.async: each thread copies two 16B granules per 128x64 tile
    const int gr = tid >> 3;                   // row 0..63
    const int gc = tid & 7;                    // 16B col group 0..7
    const uint32_t gdst0 = (uint32_t)(gr * RS + gc * 16);
    const uint32_t gdst1 = (uint32_t)((gr + 64) * RS + gc * 16);
    const size_t   gsrc0 = (size_t)gr * U_DIM + gc * 8;
    const size_t   gsrc1 = (size_t)(gr + 64) * U_DIM + gc * 8;

#define LOADC(k0, stg) do { \
        const uint32_t s = tiles + (stg) * STAGE; \
        CP16(s + ST_A_HI + gdst0, (const char*)(pAh + gsrc0 + (k0))); \
        CP16(s + ST_A_HI + gdst1, (const char*)(pAh + gsrc1 + (k0))); \
        CP16(s + ST_A_LO + gdst0, (const char*)(pAl + gsrc0 + (k0))); \
        CP16(s + ST_A_LO + gdst1, (const char*)(pAl + gsrc1 + (k0))); \
        CP16(s + ST_BF   + gdst0, (const char*)(pBf + gsrc0 + (k0))); \
        CP16(s + ST_BF   + gdst1, (const char*)(pBf + gsrc1 + (k0))); \
        CP16(s + ST_BC   + gdst0, (const char*)(pBc + gsrc0 + (k0))); \
        CP16(s + ST_BC   + gdst1, (const char*)(pBc + gsrc1 + (k0))); \
        CP_COMMIT(); \
    } while (0)

    // ldmatrix per-lane offsets
    const uint32_t aOff = (uint32_t)((mwarp * 32 + (lane & 15)) * RS + ((lane >> 4) << 4));
    // X4 B offset covering two adjacent n8 tiles
    const uint32_t bOff4 = (uint32_t)((nwarp * 32 + ((lane >> 4) << 3) + (lane & 7)) * RS +
                                      (((lane >> 3) & 1) << 4));

    float acc[2][2][4][4];   // [gate][mt][nt][e]
#pragma unroll
    for (int g = 0; g < 2; g++)
#pragma unroll
        for (int mt = 0; mt < 2; mt++)
#pragma unroll
            for (int nt = 0; nt < 4; nt++)
#pragma unroll
                for (int e = 0; e < 4; e++) acc[g][mt][nt][e] = 0.f;

    LOADC(0 * KB, 0);
    LOADC(1 * KB, 1);

    int stg = 0;            // stage of chunk i
    int nstg = 2;           // stage for chunk i+2
    for (int i = 0; i < NCHUNK; i++) {
        // groups outstanding entering chunk i: {i, i+1}; ensure group i done
        if (i < NCHUNK - 1) { CP_WAIT1(); } else { CP_WAIT0(); }
        __syncthreads();    // chunk i visible to all; all warps done reading chunk i-1
        if (i + 2 < NCHUNK) {
            LOADC((i + 2) * KB, nstg);
            nstg = (nstg == NSTAGE - 1) ? 0 : nstg + 1;
        }

        const uint32_t base = tiles + stg * STAGE;
        stg = (stg == NSTAGE - 1) ? 0 : stg + 1;
        const uint32_t aHiB = base + ST_A_HI + aOff;
        const uint32_t aLoB = base + ST_A_LO + aOff;
        const uint32_t bB[2] = { base + ST_BF + bOff4, base + ST_BC + bOff4 };

        // 4 barrier-free kk sub-iterations: ptxas can hoist kk+1 LDSMs under
        // kk MMAs, hiding the LDSM->MMA dependency the per-chunk barrier used
        // to expose every 32 k-elements.
#pragma unroll
        for (int kk = 0; kk < 4; kk++) {
            const uint32_t kb = kk * 32;  // 16 fp16 = 32 bytes
            uint32_t ah[2][4], al[2][4];
            LDSM_X4(ah[0], aHiB + kb);
            LDSM_X4(ah[1], aHiB + 16 * RS + kb);
            LDSM_X4(al[0], aLoB + kb);
            LDSM_X4(al[1], aLoB + 16 * RS + kb);
#pragma unroll
            for (int g = 0; g < 2; g++) {
                uint32_t bh[2][4];             // [pair][4 regs: nt_even(2), nt_odd(2)]
                LDSM_X4(bh[0], bB[g] + kb);
                LDSM_X4(bh[1], bB[g] + 16 * RS + kb);
                // hi sweep: 8 independent MMAs per gate
#pragma unroll
                for (int mt = 0; mt < 2; mt++)
#pragma unroll
                    for (int nt = 0; nt < 4; nt++)
                        mma_f16(acc[g][mt][nt], ah[mt], &bh[nt >> 1][(nt & 1) * 2]);
                // lo sweep: c-gate only (sigmoid damps the dropped f-gate term)
                if (g == 1) {
#pragma unroll
                    for (int mt = 0; mt < 2; mt++)
#pragma unroll
                        for (int nt = 0; nt < 4; nt++)
                            mma_f16(acc[g][mt][nt], al[mt], &bh[nt >> 1][(nt & 1) * 2]);
                }
            }
        }
    }
    __syncthreads();

    // -------- epilogue (in-register: this thread owns f and c for same elems) --------
    float ws[4] = {0.f, 0.f, 0.f, 0.f};
#pragma unroll
    for (int mt = 0; mt < 2; mt++) {
#pragma unroll
        for (int e2 = 0; e2 < 2; e2++) {
            const int rl = mwarp * 32 + mt * 16 + (lane >> 2) + e2 * 8;  // local row
            const int b = b0 + rl;
            const float x1v = g_x1[par][b];
            const __half* __restrict__ ohi = g_h_hi[par] + (size_t)b * U_DIM + u0;
            const __half* __restrict__ olo = g_h_lo[par] + (size_t)b * U_DIM + u0;
            __half* __restrict__ hhi = g_h_hi[par ^ 1] + (size_t)b * U_DIM + u0;
            __half* __restrict__ hlo = g_h_lo[par ^ 1] + (size_t)b * U_DIM + u0;
#pragma unroll
            for (int nt = 0; nt < 4; nt++) {
#pragma unroll
                for (int j = 0; j < 2; j++) {
                    const int e = e2 * 2 + j;
                    const int ul = nwarp * 32 + nt * 8 + (lane & 3) * 2 + j;  // local u (0..127)
                    const int ug = u0 + ul;
                    float xf = acc[0][mt][nt][e] + x1v * Kmat[ug] + bias[ug];
                    float xc = acc[1][mt][nt][e] + x1v * Kmat[U_DIM + ug] + bias[U_DIM + ug];
                    float fg = __fdividef(1.f, 1.f + __expf(-xf));
                    float th = 1.f - __fdividef(2.f, __expf(2.f * xc) + 1.f);
                    float ho = __half2float(ohi[ul]) + __half2float(olo[ul]);
                    float cv = fg * ho + (1.f - fg) * th;
                    __half hi = __float2half_rn(cv);
                    hhi[ul] = hi;
                    hlo[ul] = __float2half_rn(cv - __half2float(hi));
                    ws[mt * 2 + e2] += cv * wout[ug];
                }
            }
        }
    }
    // reduce ws over the 4 lanes sharing each row, then across the 4 n-warps
#pragma unroll
    for (int w = 0; w < 4; w++) {
        float v = ws[w];
        v += __shfl_xor_sync(0xFFFFFFFFu, v, 1);
        v += __shfl_xor_sync(0xFFFFFFFFu, v, 2);
        if ((lane & 3) == 0) {
            const int rl = mwarp * 32 + (w >> 1) * 16 + (lane >> 2) + (w & 1) * 8;
            red[rl * 4 + nwarp] = v;
        }
    }
    __syncthreads();
    if (tid < 128)
        g_part[b0 + tid][blockIdx.x] =
            (red[tid * 4] + red[tid * 4 + 1]) + (red[tid * 4 + 2] + red[tid * 4 + 3]);

    // -------- last-CTA-per-b-row finisher: x1/x2/out update --------
    __threadfence();
    __syncthreads();
    if (tid == 0)
        sflag[0] = atomicAdd(&g_tick[t][blockIdx.y], 1);
    __syncthreads();
    if (sflag[0] == NTILE_U - 1) {
        __threadfence();   // acquire: make other CTAs' g_part writes visible
        if (tid < 128) {
            const int b = b0 + tid;
            float dot = 0.f;
#pragma unroll
            for (int n = 0; n < NTILE_U; n++) dot += g_part[b][n];
            float x1 = g_x1[par][b], x2 = g_x2[par][b];
            float x1n = x1 + x2;
            float x2n = x2 + inp[t * B_DIM + b] * dot;
            out[t * B_DIM + b] = x1n;
            g_x1[par ^ 1][b] = x1n;
            g_x2[par ^ 1][b] = x2n;
        }
    }
}

extern "C" void kernel_launch(void* const* d_in, const int* in_sizes, int n_in,
                              void* d_out, int out_size) {
    const float* inputs = (const float*)d_in[0];   // (T, B, 1)
    const float* x1_0   = (const float*)d_in[1];   // (B, 1)
    const float* x2_0   = (const float*)d_in[2];   // (B, 1)
    const float* c0     = (const float*)d_in[3];   // (B, U)
    const float* kmat   = (const float*)d_in[4];   // (1, 2U)
    const float* rker   = (const float*)d_in[5];   // (U, 2U)
    const float* bias   = (const float*)d_in[6];   // (2U)
    const float* wout   = (const float*)d_in[7];   // (U, 1)
    float* out = (float*)d_out;                    // (T, B, 1)
    (void)in_sizes; (void)n_in; (void)out_size;

    cudaFuncSetAttribute(step_gemm, cudaFuncAttributeMaxDynamicSharedMemorySize, SMEM_REQ);

    init_state<<<1024, 256>>>(x1_0, x2_0, c0);
    transpose_R<<<dim3(2 * U_DIM / 32, U_DIM / 32), dim3(32, 8)>>>(rker);

    dim3 grid(NTILE_U, NTILE_B);  // (8, 16)
    for (int t = 0; t < T_STEPS; t++)
        step_gemm<<<grid, 512, SMEM_REQ>>>(kmat, bias, wout, inputs, out, t);
}

// round 16
// speedup vs baseline: 1.4768x; 1.4768x over previous
#include <cuda_runtime.h>
#include <cuda_fp16.h>
#include <cstdint>
#include <math.h>

#define T_STEPS 64
#define B_DIM 2048
#define U_DIM 1024
#define NTILE_U 8             // 1024/128 u-tiles
#define NTILE_B 16            // 2048/128 b-tiles
#define KB 32                 // k elements per chunk
#define NCHUNK (U_DIM / KB)   // 32

// ---------------- persistent state (no allocs allowed) ----------------
__device__ __align__(128) __half g_h_hi[2][B_DIM * U_DIM];
__device__ __align__(128) __half g_h_lo[2][B_DIM * U_DIM];
__device__ __align__(128) __half g_Rt[2 * U_DIM * U_DIM];   // Rt[n][k] = R[k][n], rounded fp16
__device__ float g_x1[2][B_DIM];
__device__ float g_x2[2][B_DIM];
__device__ float g_part[B_DIM][NTILE_U];
__device__ int   g_tick[T_STEPS][NTILE_B];

// ---------------- PTX helpers (base-sm_103-safe) ----------------
__device__ __forceinline__ uint32_t smem_u32(const void* p) {
    uint32_t a;
    asm("{ .reg .u64 t; cvta.to.shared.u64 t, %1; cvt.u32.u64 %0, t; }" : "=r"(a) : "l"(p));
    return a;
}
#define CP16(s, g) \
    asm volatile("cp.async.cg.shared.global [%0], [%1], 16;" :: "r"(s), "l"(g) : "memory")
#define CP_COMMIT() asm volatile("cp.async.commit_group;" ::: "memory")
#define CP_WAIT2()  asm volatile("cp.async.wait_group 2;" ::: "memory")
#define CP_WAIT1()  asm volatile("cp.async.wait_group 1;" ::: "memory")
#define CP_WAIT0()  asm volatile("cp.async.wait_group 0;" ::: "memory")

#define LDSM_X4(r, addr) \
    asm volatile("ldmatrix.sync.aligned.m8n8.x4.shared.b16 {%0,%1,%2,%3}, [%4];" \
        : "=r"((r)[0]), "=r"((r)[1]), "=r"((r)[2]), "=r"((r)[3]) : "r"(addr))

__device__ __forceinline__ void mma_f16(float* d, const uint32_t* a, const uint32_t* b) {
    asm volatile("mma.sync.aligned.m16n8k16.row.col.f32.f16.f16.f32 "
        "{%0,%1,%2,%3}, {%4,%5,%6,%7}, {%8,%9}, {%0,%1,%2,%3};"
        : "+f"(d[0]), "+f"(d[1]), "+f"(d[2]), "+f"(d[3])
        : "r"(a[0]), "r"(a[1]), "r"(a[2]), "r"(a[3]), "r"(b[0]), "r"(b[1]));
}

// SMEM stage layout: 4 tiles of 128 rows x 32 k fp16, padded row stride 80 B
#define RS 80
#define TILE_B (128 * RS)       // 10240
#define ST_A_HI 0
#define ST_A_LO (1 * TILE_B)
#define ST_BF   (2 * TILE_B)
#define ST_BC   (3 * TILE_B)
#define STAGE (4 * TILE_B)      // 40960
#define NSTAGE 4
#define SMEM_HDR 3072           // red[128][4] floats (2048) + sflag + pad
#define SMEM_REQ (SMEM_HDR + NSTAGE * STAGE)   // ~167 KB

// ---------------- init kernels ----------------
__global__ void init_state(const float* __restrict__ x1_0,
                           const float* __restrict__ x2_0,
                           const float* __restrict__ c0) {
    int i = blockIdx.x * blockDim.x + threadIdx.x;
    int stride = gridDim.x * blockDim.x;
    if (i < B_DIM) { g_x1[0][i] = x1_0[i]; g_x2[0][i] = x2_0[i]; }
    if (i < T_STEPS * NTILE_B) ((int*)g_tick)[i] = 0;
    for (int j = i; j < B_DIM * U_DIM; j += stride) {
        float v = c0[j];
        __half hi = __float2half_rn(v);
        g_h_hi[0][j] = hi;
        g_h_lo[0][j] = __float2half_rn(v - __half2float(hi));
    }
}

// Transpose R (U x 2U, row-major) -> Rt (2U x U), rounded to fp16.
__global__ void transpose_R(const float* __restrict__ R) {
    __shared__ float tile[32][33];
    const int nb = blockIdx.x * 32;   // n tile (0..2047)
    const int kb = blockIdx.y * 32;   // k tile (0..1023)
    const int tx = threadIdx.x, ty = threadIdx.y;
    for (int kk = ty; kk < 32; kk += 8)
        tile[kk][tx] = R[(kb + kk) * (2 * U_DIM) + nb + tx];
    __syncthreads();
    for (int nn = ty; nn < 32; nn += 8)
        g_Rt[(size_t)(nb + nn) * U_DIM + kb + tx] = __float2half_rn(tile[tx][nn]);
}

// ---------------- main step kernel ----------------
// grid (8 u-tiles, 16 b-tiles) = 128 CTAs, 512 threads, occ 1 => one CTA per SM.
__global__ __launch_bounds__(512, 1)
void step_gemm(const float* __restrict__ Kmat,   // (2U)
               const float* __restrict__ bias,   // (2U)
               const float* __restrict__ wout,   // (U)
               const float* __restrict__ inp,    // (T, B)
               float* __restrict__ out,          // (T, B)
               int t)
{
    extern __shared__ char smem[];
    float* red = (float*)smem;                 // [128][4]
    int* sflag = (int*)(smem + 2048);
    const uint32_t sb = smem_u32(smem);
    const uint32_t tiles = sb + SMEM_HDR;
    const int par = t & 1;

    const int tid  = threadIdx.x;
    const int lane = tid & 31;
    const int wid  = tid >> 5;                 // 0..15
    const int mwarp = wid & 3;                 // 4 x 32 rows
    const int nwarp = wid >> 2;                // 4 x 32 cols
    const int b0 = blockIdx.y * 128;
    const int u0 = blockIdx.x * 128;

    const __half* __restrict__ pAh = g_h_hi[par] + (size_t)b0 * U_DIM;
    const __half* __restrict__ pAl = g_h_lo[par] + (size_t)b0 * U_DIM;
    const __half* __restrict__ pBf = g_Rt + (size_t)u0 * U_DIM;
    const __half* __restrict__ pBc = g_Rt + (size_t)(U_DIM + u0) * U_DIM;

    // cp.async: each of 512 threads copies one 16B granule per 128x32 tile
    const int gr = tid >> 2;                   // row 0..127
    const int gc = tid & 3;                    // 16B col group
    const uint32_t gdst = (uint32_t)(gr * RS + gc * 16);
    const size_t   gsrc = (size_t)gr * U_DIM + gc * 8;

#define LOADC(k0, stg) do { \
        const uint32_t s = tiles + (stg) * STAGE; \
        CP16(s + ST_A_HI + gdst, (const char*)(pAh + gsrc + (k0))); \
        CP16(s + ST_A_LO + gdst, (const char*)(pAl + gsrc + (k0))); \
        CP16(s + ST_BF   + gdst, (const char*)(pBf + gsrc + (k0))); \
        CP16(s + ST_BC   + gdst, (const char*)(pBc + gsrc + (k0))); \
        CP_COMMIT(); \
    } while (0)

    // ldmatrix per-lane offsets
    const uint32_t aOff = (uint32_t)((mwarp * 32 + (lane & 15)) * RS + ((lane >> 4) << 4));
    // X4 B offset covering two adjacent n8 tiles
    const uint32_t bOff4 = (uint32_t)((nwarp * 32 + ((lane >> 4) << 3) + (lane & 7)) * RS +
                                      (((lane >> 3) & 1) << 4));

    float acc[2][2][4][4];   // [gate][mt][nt][e]
#pragma unroll
    for (int g = 0; g < 2; g++)
#pragma unroll
        for (int mt = 0; mt < 2; mt++)
#pragma unroll
            for (int nt = 0; nt < 4; nt++)
#pragma unroll
                for (int e = 0; e < 4; e++) acc[g][mt][nt][e] = 0.f;

    LOADC(0 * KB, 0);
    LOADC(1 * KB, 1);
    LOADC(2 * KB, 2);

    int stg = 0;            // stage of chunk i
    int nstg = 3;           // stage for chunk i+3
    for (int i = 0; i < NCHUNK; i++) {
        // ensure chunk i's cp.async group completed
        if (i < NCHUNK - 2)      { CP_WAIT2(); }
        else if (i == NCHUNK - 2){ CP_WAIT1(); }
        else                     { CP_WAIT0(); }
        __syncthreads();    // chunk i visible to all; all warps done reading chunk i-1
        if (i + 3 < NCHUNK) {
            LOADC((i + 3) * KB, nstg);
            nstg = (nstg == NSTAGE - 1) ? 0 : nstg + 1;
        }

        const uint32_t base = tiles + stg * STAGE;
        stg = (stg == NSTAGE - 1) ? 0 : stg + 1;
        const uint32_t aHiB = base + ST_A_HI + aOff;
        const uint32_t aLoB = base + ST_A_LO + aOff;
        const uint32_t bfB = base + ST_BF + bOff4;
        const uint32_t bcB = base + ST_BC + bOff4;

#pragma unroll
        for (int kk = 0; kk < 2; kk++) {
            const uint32_t kb = kk * 32;  // 16 fp16 = 32 bytes
            // ALL fragment loads of this kk issue back-to-back BEFORE any MMA:
            // the 24-MMA stream then covers the smem latency of the later
            // LDSMs instead of exposing the c-gate B-load mid-iteration.
            uint32_t ah[2][4], al[2][4], bf[2][4], bc[2][4];
            LDSM_X4(ah[0], aHiB + kb);
            LDSM_X4(ah[1], aHiB + 16 * RS + kb);
            LDSM_X4(al[0], aLoB + kb);
            LDSM_X4(al[1], aLoB + 16 * RS + kb);
            LDSM_X4(bf[0], bfB + kb);
            LDSM_X4(bf[1], bfB + 16 * RS + kb);
            LDSM_X4(bc[0], bcB + kb);
            LDSM_X4(bc[1], bcB + 16 * RS + kb);
            // f-gate hi sweep (8 independent MMAs)
#pragma unroll
            for (int mt = 0; mt < 2; mt++)
#pragma unroll
                for (int nt = 0; nt < 4; nt++)
                    mma_f16(acc[0][mt][nt], ah[mt], &bf[nt >> 1][(nt & 1) * 2]);
            // c-gate hi sweep
#pragma unroll
            for (int mt = 0; mt < 2; mt++)
#pragma unroll
                for (int nt = 0; nt < 4; nt++)
                    mma_f16(acc[1][mt][nt], ah[mt], &bc[nt >> 1][(nt & 1) * 2]);
            // c-gate lo sweep (f-gate's dropped lo term is sigmoid-damped)
#pragma unroll
            for (int mt = 0; mt < 2; mt++)
#pragma unroll
                for (int nt = 0; nt < 4; nt++)
                    mma_f16(acc[1][mt][nt], al[mt], &bc[nt >> 1][(nt & 1) * 2]);
        }
    }
    __syncthreads();

    // -------- epilogue (in-register: this thread owns f and c for same elems) --------
    float ws[4] = {0.f, 0.f, 0.f, 0.f};
#pragma unroll
    for (int mt = 0; mt < 2; mt++) {
#pragma unroll
        for (int e2 = 0; e2 < 2; e2++) {
            const int rl = mwarp * 32 + mt * 16 + (lane >> 2) + e2 * 8;  // local row
            const int b = b0 + rl;
            const float x1v = g_x1[par][b];
            const __half* __restrict__ ohi = g_h_hi[par] + (size_t)b * U_DIM + u0;
            const __half* __restrict__ olo = g_h_lo[par] + (size_t)b * U_DIM + u0;
            __half* __restrict__ hhi = g_h_hi[par ^ 1] + (size_t)b * U_DIM + u0;
            __half* __restrict__ hlo = g_h_lo[par ^ 1] + (size_t)b * U_DIM + u0;
#pragma unroll
            for (int nt = 0; nt < 4; nt++) {
#pragma unroll
                for (int j = 0; j < 2; j++) {
                    const int e = e2 * 2 + j;
                    const int ul = nwarp * 32 + nt * 8 + (lane & 3) * 2 + j;  // local u (0..127)
                    const int ug = u0 + ul;
                    float xf = acc[0][mt][nt][e] + x1v * Kmat[ug] + bias[ug];
                    float xc = acc[1][mt][nt][e] + x1v * Kmat[U_DIM + ug] + bias[U_DIM + ug];
                    float fg = __fdividef(1.f, 1.f + __expf(-xf));
                    float th = 1.f - __fdividef(2.f, __expf(2.f * xc) + 1.f);
                    float ho = __half2float(ohi[ul]) + __half2float(olo[ul]);
                    float cv = fg * ho + (1.f - fg) * th;
                    __half hi = __float2half_rn(cv);
                    hhi[ul] = hi;
                    hlo[ul] = __float2half_rn(cv - __half2float(hi));
                    ws[mt * 2 + e2] += cv * wout[ug];
                }
            }
        }
    }
    // reduce ws over the 4 lanes sharing each row, then across the 4 n-warps
#pragma unroll
    for (int w = 0; w < 4; w++) {
        float v = ws[w];
        v += __shfl_xor_sync(0xFFFFFFFFu, v, 1);
        v += __shfl_xor_sync(0xFFFFFFFFu, v, 2);
        if ((lane & 3) == 0) {
            const int rl = mwarp * 32 + (w >> 1) * 16 + (lane >> 2) + (w & 1) * 8;
            red[rl * 4 + nwarp] = v;
        }
    }
    __syncthreads();
    if (tid < 128)
        g_part[b0 + tid][blockIdx.x] =
            (red[tid * 4] + red[tid * 4 + 1]) + (red[tid * 4 + 2] + red[tid * 4 + 3]);

    // -------- last-CTA-per-b-row finisher: x1/x2/out update --------
    __threadfence();
    __syncthreads();
    if (tid == 0)
        sflag[0] = atomicAdd(&g_tick[t][blockIdx.y], 1);
    __syncthreads();
    if (sflag[0] == NTILE_U - 1) {
        __threadfence();   // acquire: make other CTAs' g_part writes visible
        if (tid < 128) {
            const int b = b0 + tid;
            float dot = 0.f;
#pragma unroll
            for (int n = 0; n < NTILE_U; n++) dot += g_part[b][n];
            float x1 = g_x1[par][b], x2 = g_x2[par][b];
            float x1n = x1 + x2;
            float x2n = x2 + inp[t * B_DIM + b] * dot;
            out[t * B_DIM + b] = x1n;
            g_x1[par ^ 1][b] = x1n;
            g_x2[par ^ 1][b] = x2n;
        }
    }
}

extern "C" void kernel_launch(void* const* d_in, const int* in_sizes, int n_in,
                              void* d_out, int out_size) {
    const float* inputs = (const float*)d_in[0];   // (T, B, 1)
    const float* x1_0   = (const float*)d_in[1];   // (B, 1)
    const float* x2_0   = (const float*)d_in[2];   // (B, 1)
    const float* c0     = (const float*)d_in[3];   // (B, U)
    const float* kmat   = (const float*)d_in[4];   // (1, 2U)
    const float* rker   = (const float*)d_in[5];   // (U, 2U)
    const float* bias   = (const float*)d_in[6];   // (2U)
    const float* wout   = (const float*)d_in[7];   // (U, 1)
    float* out = (float*)d_out;                    // (T, B, 1)
    (void)in_sizes; (void)n_in; (void)out_size;

    cudaFuncSetAttribute(step_gemm, cudaFuncAttributeMaxDynamicSharedMemorySize, SMEM_REQ);

    init_state<<<1024, 256>>>(x1_0, x2_0, c0);
    transpose_R<<<dim3(2 * U_DIM / 32, U_DIM / 32), dim3(32, 8)>>>(rker);

    dim3 grid(NTILE_U, NTILE_B);  // (8, 16)
    for (int t = 0; t < T_STEPS; t++)
        step_gemm<<<grid, 512, SMEM_REQ>>>(kmat, bias, wout, inputs, out, t);
}

// round 17
// speedup vs baseline: 1.4931x; 1.0110x over previous
#include <cuda_runtime.h>
#include <cuda_fp16.h>
#include <cstdint>
#include <math.h>

#define T_STEPS 64
#define B_DIM 2048
#define U_DIM 1024
#define NTILE_U 8             // 1024/128 u-tiles
#define NTILE_B 16            // 2048/128 b-tiles
#define KB 32                 // k elements per chunk
#define NCHUNK (U_DIM / KB)   // 32

// ---------------- persistent state (no allocs allowed) ----------------
__device__ __align__(128) __half g_h_hi[2][B_DIM * U_DIM];
__device__ __align__(128) __half g_h_lo[2][B_DIM * U_DIM];
__device__ __align__(128) __half g_Rt[2 * U_DIM * U_DIM];   // Rt[n][k] = R[k][n], rounded fp16
__device__ float g_x1[2][B_DIM];
__device__ float g_x2[2][B_DIM];
__device__ float g_part[B_DIM][NTILE_U];
__device__ int   g_tick[T_STEPS][NTILE_B];
__device__ int   g_flag[T_STEPS][NTILE_B];   // row-(t) complete: h, x1, x2 ready

// ---------------- PTX helpers (base-sm_103-safe) ----------------
__device__ __forceinline__ uint32_t smem_u32(const void* p) {
    uint32_t a;
    asm("{ .reg .u64 t; cvta.to.shared.u64 t, %1; cvt.u32.u64 %0, t; }" : "=r"(a) : "l"(p));
    return a;
}
#define CP16(s, g) \
    asm volatile("cp.async.cg.shared.global [%0], [%1], 16;" :: "r"(s), "l"(g) : "memory")
#define CP_COMMIT() asm volatile("cp.async.commit_group;" ::: "memory")
#define CP_WAIT2()  asm volatile("cp.async.wait_group 2;" ::: "memory")
#define CP_WAIT1()  asm volatile("cp.async.wait_group 1;" ::: "memory")
#define CP_WAIT0()  asm volatile("cp.async.wait_group 0;" ::: "memory")

#define LDSM_X4(r, addr) \
    asm volatile("ldmatrix.sync.aligned.m8n8.x4.shared.b16 {%0,%1,%2,%3}, [%4];" \
        : "=r"((r)[0]), "=r"((r)[1]), "=r"((r)[2]), "=r"((r)[3]) : "r"(addr))

__device__ __forceinline__ void mma_f16(float* d, const uint32_t* a, const uint32_t* b) {
    asm volatile("mma.sync.aligned.m16n8k16.row.col.f32.f16.f16.f32 "
        "{%0,%1,%2,%3}, {%4,%5,%6,%7}, {%8,%9}, {%0,%1,%2,%3};"
        : "+f"(d[0]), "+f"(d[1]), "+f"(d[2]), "+f"(d[3])
        : "r"(a[0]), "r"(a[1]), "r"(a[2]), "r"(a[3]), "r"(b[0]), "r"(b[1]));
}

// SMEM stage layout: 4 tiles of 128 rows x 32 k fp16, padded row stride 80 B
#define RS 80
#define TILE_B (128 * RS)       // 10240
#define ST_A_HI 0
#define ST_A_LO (1 * TILE_B)
#define ST_BF   (2 * TILE_B)
#define ST_BC   (3 * TILE_B)
#define STAGE (4 * TILE_B)      // 40960
#define NSTAGE 4
#define SMEM_HDR 3072           // red[128][4] floats (2048) + sflag + pad
#define SMEM_REQ (SMEM_HDR + NSTAGE * STAGE)   // ~167 KB

// ---------------- init kernels ----------------
__global__ void init_state(const float* __restrict__ x1_0,
                           const float* __restrict__ x2_0,
                           const float* __restrict__ c0) {
    int i = blockIdx.x * blockDim.x + threadIdx.x;
    int stride = gridDim.x * blockDim.x;
    if (i < B_DIM) { g_x1[0][i] = x1_0[i]; g_x2[0][i] = x2_0[i]; }
    if (i < T_STEPS * NTILE_B) { ((int*)g_tick)[i] = 0; ((int*)g_flag)[i] = 0; }
    for (int j = i; j < B_DIM * U_DIM; j += stride) {
        float v = c0[j];
        __half hi = __float2half_rn(v);
        g_h_hi[0][j] = hi;
        g_h_lo[0][j] = __float2half_rn(v - __half2float(hi));
    }
}

// Transpose R (U x 2U, row-major) -> Rt (2U x U), rounded to fp16.
__global__ void transpose_R(const float* __restrict__ R) {
    __shared__ float tile[32][33];
    const int nb = blockIdx.x * 32;   // n tile (0..2047)
    const int kb = blockIdx.y * 32;   // k tile (0..1023)
    const int tx = threadIdx.x, ty = threadIdx.y;
    for (int kk = ty; kk < 32; kk += 8)
        tile[kk][tx] = R[(kb + kk) * (2 * U_DIM) + nb + tx];
    __syncthreads();
    for (int nn = ty; nn < 32; nn += 8)
        g_Rt[(size_t)(nb + nn) * U_DIM + kb + tx] = __float2half_rn(tile[tx][nn]);
}

// ---------------- persistent step kernel ----------------
// grid (8 u-tiles, 16 b-tiles) = 128 CTAs, occ 1 => all co-resident (148 SMs).
// One launch runs all T_STEPS; CTA (u,row) at step t waits only on row's flag
// from step t-1 (per-row dataflow instead of a full-grid barrier per step).
__global__ __launch_bounds__(512, 1)
void step_persist(const float* __restrict__ Kmat,   // (2U)
                  const float* __restrict__ bias,   // (2U)
                  const float* __restrict__ wout,   // (U)
                  const float* __restrict__ inp,    // (T, B)
                  float* __restrict__ out)          // (T, B)
{
    extern __shared__ char smem[];
    float* red = (float*)smem;                 // [128][4]
    int* sflag = (int*)(smem + 2048);
    const uint32_t sb = smem_u32(smem);
    const uint32_t tiles = sb + SMEM_HDR;

    const int tid  = threadIdx.x;
    const int lane = tid & 31;
    const int wid  = tid >> 5;                 // 0..15
    const int mwarp = wid & 3;                 // 4 x 32 rows
    const int nwarp = wid >> 2;                // 4 x 32 cols
    const int b0 = blockIdx.y * 128;
    const int u0 = blockIdx.x * 128;
    const int row = blockIdx.y;

    // step-invariant pointers / offsets
    const __half* __restrict__ pBf = g_Rt + (size_t)u0 * U_DIM;
    const __half* __restrict__ pBc = g_Rt + (size_t)(U_DIM + u0) * U_DIM;
    const int gr = tid >> 2;                   // cp.async row 0..127
    const int gc = tid & 3;                    // 16B col group
    const uint32_t gdst = (uint32_t)(gr * RS + gc * 16);
    const size_t   gsrc = (size_t)gr * U_DIM + gc * 8;
    const uint32_t aOff = (uint32_t)((mwarp * 32 + (lane & 15)) * RS + ((lane >> 4) << 4));
    const uint32_t bOff4 = (uint32_t)((nwarp * 32 + ((lane >> 4) << 3) + (lane & 7)) * RS +
                                      (((lane >> 3) & 1) << 4));

    for (int t = 0; t < T_STEPS; t++) {
        const int par = t & 1;

        // ---- wait for this row's step t-1 to complete (h, x1, x2 ready) ----
        if (t > 0) {
            if (tid == 0) {
                volatile int* f = &g_flag[t - 1][row];
                while (*f == 0) { __nanosleep(64); }
            }
            __syncthreads();
            __threadfence();   // gpu-scope fence: CCTL.IVALL invalidates L1D, so
                               // plain LDGs below cannot hit lines cached at step t-2
        }

        const __half* __restrict__ pAh = g_h_hi[par] + (size_t)b0 * U_DIM;
        const __half* __restrict__ pAl = g_h_lo[par] + (size_t)b0 * U_DIM;

#define LOADC(k0, stg) do { \
        const uint32_t s = tiles + (stg) * STAGE; \
        CP16(s + ST_A_HI + gdst, (const char*)(pAh + gsrc + (k0))); \
        CP16(s + ST_A_LO + gdst, (const char*)(pAl + gsrc + (k0))); \
        CP16(s + ST_BF   + gdst, (const char*)(pBf + gsrc + (k0))); \
        CP16(s + ST_BC   + gdst, (const char*)(pBc + gsrc + (k0))); \
        CP_COMMIT(); \
    } while (0)

        float acc[2][2][4][4];   // [gate][mt][nt][e]
#pragma unroll
        for (int g = 0; g < 2; g++)
#pragma unroll
            for (int mt = 0; mt < 2; mt++)
#pragma unroll
                for (int nt = 0; nt < 4; nt++)
#pragma unroll
                    for (int e = 0; e < 4; e++) acc[g][mt][nt][e] = 0.f;

        LOADC(0 * KB, 0);
        LOADC(1 * KB, 1);
        LOADC(2 * KB, 2);

        int stg = 0;            // stage of chunk i
        int nstg = 3;           // stage for chunk i+3
        for (int i = 0; i < NCHUNK; i++) {
            if (i < NCHUNK - 2)      { CP_WAIT2(); }
            else if (i == NCHUNK - 2){ CP_WAIT1(); }
            else                     { CP_WAIT0(); }
            __syncthreads();
            if (i + 3 < NCHUNK) {
                LOADC((i + 3) * KB, nstg);
                nstg = (nstg == NSTAGE - 1) ? 0 : nstg + 1;
            }

            const uint32_t base = tiles + stg * STAGE;
            stg = (stg == NSTAGE - 1) ? 0 : stg + 1;
            const uint32_t aHiB = base + ST_A_HI + aOff;
            const uint32_t aLoB = base + ST_A_LO + aOff;
            const uint32_t bfB = base + ST_BF + bOff4;
            const uint32_t bcB = base + ST_BC + bOff4;

#pragma unroll
            for (int kk = 0; kk < 2; kk++) {
                const uint32_t kb = kk * 32;  // 16 fp16 = 32 bytes
                uint32_t ah[2][4], al[2][4];
                LDSM_X4(ah[0], aHiB + kb);
                LDSM_X4(ah[1], aHiB + 16 * RS + kb);
                LDSM_X4(al[0], aLoB + kb);
                LDSM_X4(al[1], aLoB + 16 * RS + kb);
                {
                    uint32_t bf[2][4];
                    LDSM_X4(bf[0], bfB + kb);
                    LDSM_X4(bf[1], bfB + 16 * RS + kb);
#pragma unroll
                    for (int mt = 0; mt < 2; mt++)
#pragma unroll
                        for (int nt = 0; nt < 4; nt++)
                            mma_f16(acc[0][mt][nt], ah[mt], &bf[nt >> 1][(nt & 1) * 2]);
                }
                {
                    uint32_t bc[2][4];
                    LDSM_X4(bc[0], bcB + kb);
                    LDSM_X4(bc[1], bcB + 16 * RS + kb);
#pragma unroll
                    for (int mt = 0; mt < 2; mt++)
#pragma unroll
                        for (int nt = 0; nt < 4; nt++)
                            mma_f16(acc[1][mt][nt], ah[mt], &bc[nt >> 1][(nt & 1) * 2]);
#pragma unroll
                    for (int mt = 0; mt < 2; mt++)
#pragma unroll
                        for (int nt = 0; nt < 4; nt++)
                            mma_f16(acc[1][mt][nt], al[mt], &bc[nt >> 1][(nt & 1) * 2]);
                }
            }
        }
        __syncthreads();

        // -------- epilogue --------
        float ws[4] = {0.f, 0.f, 0.f, 0.f};
#pragma unroll
        for (int mt = 0; mt < 2; mt++) {
#pragma unroll
            for (int e2 = 0; e2 < 2; e2++) {
                const int rl = mwarp * 32 + mt * 16 + (lane >> 2) + e2 * 8;  // local row
                const int b = b0 + rl;
                const float x1v = g_x1[par][b];
                const __half* __restrict__ ohi = g_h_hi[par] + (size_t)b * U_DIM + u0;
                const __half* __restrict__ olo = g_h_lo[par] + (size_t)b * U_DIM + u0;
                __half* __restrict__ hhi = g_h_hi[par ^ 1] + (size_t)b * U_DIM + u0;
                __half* __restrict__ hlo = g_h_lo[par ^ 1] + (size_t)b * U_DIM + u0;
#pragma unroll
                for (int nt = 0; nt < 4; nt++) {
#pragma unroll
                    for (int j = 0; j < 2; j++) {
                        const int e = e2 * 2 + j;
                        const int ul = nwarp * 32 + nt * 8 + (lane & 3) * 2 + j;  // local u
                        const int ug = u0 + ul;
                        float xf = acc[0][mt][nt][e] + x1v * Kmat[ug] + bias[ug];
                        float xc = acc[1][mt][nt][e] + x1v * Kmat[U_DIM + ug] + bias[U_DIM + ug];
                        float fg = __fdividef(1.f, 1.f + __expf(-xf));
                        float th = 1.f - __fdividef(2.f, __expf(2.f * xc) + 1.f);
                        float ho = __half2float(ohi[ul]) + __half2float(olo[ul]);
                        float cv = fg * ho + (1.f - fg) * th;
                        __half hi = __float2half_rn(cv);
                        hhi[ul] = hi;
                        hlo[ul] = __float2half_rn(cv - __half2float(hi));
                        ws[mt * 2 + e2] += cv * wout[ug];
                    }
                }
            }
        }
#pragma unroll
        for (int w = 0; w < 4; w++) {
            float v = ws[w];
            v += __shfl_xor_sync(0xFFFFFFFFu, v, 1);
            v += __shfl_xor_sync(0xFFFFFFFFu, v, 2);
            if ((lane & 3) == 0) {
                const int rl = mwarp * 32 + (w >> 1) * 16 + (lane >> 2) + (w & 1) * 8;
                red[rl * 4 + nwarp] = v;
            }
        }
        __syncthreads();
        if (tid < 128)
            g_part[b0 + tid][blockIdx.x] =
                (red[tid * 4] + red[tid * 4 + 1]) + (red[tid * 4 + 2] + red[tid * 4 + 3]);

        // -------- row ticket; last CTA finishes the row and raises the flag --------
        __threadfence();   // release: h + g_part visible before ticket
        __syncthreads();
        if (tid == 0)
            sflag[0] = atomicAdd(&g_tick[t][row], 1);
        __syncthreads();
        if (sflag[0] == NTILE_U - 1) {
            __threadfence();   // acquire + L1 invalidate: fresh g_part from peers
            if (tid < 128) {
                const int b = b0 + tid;
                float dot = 0.f;
#pragma unroll
                for (int n = 0; n < NTILE_U; n++) dot += g_part[b][n];
                float x1 = g_x1[par][b], x2 = g_x2[par][b];
                float x1n = x1 + x2;
                float x2n = x2 + inp[t * B_DIM + b] * dot;
                out[t * B_DIM + b] = x1n;
                g_x1[par ^ 1][b] = x1n;
                g_x2[par ^ 1][b] = x2n;
            }
            __syncthreads();
            __threadfence();   // release: x1/x2/out visible before flag
            if (tid == 0)
                atomicExch(&g_flag[t][row], 1);
        }
    }
}

extern "C" void kernel_launch(void* const* d_in, const int* in_sizes, int n_in,
                              void* d_out, int out_size) {
    const float* inputs = (const float*)d_in[0];   // (T, B, 1)
    const float* x1_0   = (const float*)d_in[1];   // (B, 1)
    const float* x2_0   = (const float*)d_in[2];   // (B, 1)
    const float* c0     = (const float*)d_in[3];   // (B, U)
    const float* kmat   = (const float*)d_in[4];   // (1, 2U)
    const float* rker   = (const float*)d_in[5];   // (U, 2U)
    const float* bias   = (const float*)d_in[6];   // (2U)
    const float* wout   = (const float*)d_in[7];   // (U, 1)
    float* out = (float*)d_out;                    // (T, B, 1)
    (void)in_sizes; (void)n_in; (void)out_size;

    cudaFuncSetAttribute(step_persist, cudaFuncAttributeMaxDynamicSharedMemorySize, SMEM_REQ);

    init_state<<<1024, 256>>>(x1_0, x2_0, c0);
    transpose_R<<<dim3(2 * U_DIM / 32, U_DIM / 32), dim3(32, 8)>>>(rker);

    dim3 grid(NTILE_U, NTILE_B);  // (8, 16) = 128 CTAs, all co-resident
    step_persist<<<grid, 512, SMEM_REQ>>>(kmat, bias, wout, inputs, out);
}